// round 16
// baseline (speedup 1.0000x reference)
#include <cuda_runtime.h>
#include <cuda_bf16.h>
#include <cuda_fp16.h>
#include <math.h>
#include <cstdint>

// Problem constants
#define BDIM   4
#define SEQ    2048
#define DMODEL 1024
#define NH     16
#define HD     64
#define SCALE  0.125f            // 1/sqrt(64)

// ============================================================================
// mma.sync / ldmatrix / cp.async helpers (base sm_80+ PTX, compute_103-safe)
// ============================================================================
__device__ __forceinline__ void mma16816h(float* c, const uint32_t* a, const uint32_t* b) {
    asm volatile("mma.sync.aligned.m16n8k16.row.col.f32.f16.f16.f32 "
        "{%0,%1,%2,%3}, {%4,%5,%6,%7}, {%8,%9}, {%0,%1,%2,%3};"
        : "+f"(c[0]), "+f"(c[1]), "+f"(c[2]), "+f"(c[3])
        : "r"(a[0]), "r"(a[1]), "r"(a[2]), "r"(a[3]), "r"(b[0]), "r"(b[1]));
}
__device__ __forceinline__ void ldsm4(uint32_t* r, uint32_t addr) {
    asm volatile("ldmatrix.sync.aligned.m8n8.x4.shared.b16 {%0,%1,%2,%3}, [%4];"
        : "=r"(r[0]), "=r"(r[1]), "=r"(r[2]), "=r"(r[3]) : "r"(addr));
}
__device__ __forceinline__ void ldsm4t(uint32_t* r, uint32_t addr) {
    asm volatile("ldmatrix.sync.aligned.m8n8.x4.trans.shared.b16 {%0,%1,%2,%3}, [%4];"
        : "=r"(r[0]), "=r"(r[1]), "=r"(r[2]), "=r"(r[3]) : "r"(addr));
}
__device__ __forceinline__ uint32_t smem_u32(const void* p) {
    uint32_t a;
    asm("{ .reg .u64 t; cvta.to.shared.u64 t, %1; cvt.u32.u64 %0, t; }"
        : "=r"(a) : "l"(p));
    return a;
}
__device__ __forceinline__ void cp16(uint32_t s, const void* g) {
    asm volatile("cp.async.cg.shared.global [%0], [%1], 16;" :: "r"(s), "l"(g));
}
#define CP_COMMIT() asm volatile("cp.async.commit_group;" ::: "memory")
#define CP_WAIT(n)  asm volatile("cp.async.wait_group %0;" :: "n"(n) : "memory")

__device__ __forceinline__ uint32_t hpair(float x, float y) {
    __half2 p;
    p.x = __float2half_rn(x); p.y = __float2half_rn(y);
    return *(uint32_t*)&p;
}

// ============================================================================
// scratch (device globals: no allocation allowed)
// ============================================================================
__device__ __half g_x  [8192*1024];          // X fp16 (single)
__device__ __half g_wq [3072*1024];          // W_qkv^T fp16 (single) [N,K]
__device__ __half g_wp [1024*1024];          // W_proj^T fp16 (single) [N,K]
__device__ __half g_qh[BDIM*NH*SEQ*HD];      // q fp16 (pre-scaled) [B,H,S,hd]
__device__ __half g_kh[BDIM*NH*SEQ*HD];      // k fp16
__device__ __half g_vh[BDIM*NH*SEQ*HD];      // v fp16
__device__ __half g_ah[8192*1024];           // attn out fp16 [B,S,D]

// ============================================================================
// Pre-pass: convert X to fp16
// ============================================================================
__global__ __launch_bounds__(256) void conv_x(const float* __restrict__ x,
                                              __half* __restrict__ dh)
{
    size_t i = ((size_t)blockIdx.x * 256 + threadIdx.x) * 4;
    float4 v = *(const float4*)(x + i);
    *(uint32_t*)(dh + i)     = hpair(v.x, v.y);
    *(uint32_t*)(dh + i + 2) = hpair(v.z, v.w);
}

// ============================================================================
// Pre-pass: transpose W [K=1024, N] -> W^T fp16 [N, 1024]
// ============================================================================
__global__ __launch_bounds__(256) void split_tr(const float* __restrict__ src,
                                                __half* __restrict__ dh,
                                                int N)
{
    __shared__ float t[32][33];
    const int n0 = blockIdx.x * 32, k0 = blockIdx.y * 32;
    const int tx = threadIdx.x & 31, ty = threadIdx.x >> 5;   // ty 0..7
    #pragma unroll
    for (int r = 0; r < 4; r++) {
        int k = k0 + ty + r * 8;
        t[ty + r * 8][tx] = src[(size_t)k * N + n0 + tx];
    }
    __syncthreads();
    #pragma unroll
    for (int r = 0; r < 4; r++) {
        int n = n0 + ty + r * 8;
        dh[(size_t)n * 1024 + k0 + tx] = __float2half_rn(t[tx][ty + r * 8]);
    }
}

// ============================================================================
// GEMM via mma.sync + cp.async: C[128,128]=A@B^T, A,B single fp16.
// BK=64 (16 chunks — halves per-chunk fixed overhead), 2-stage,
// one sync per chunk, 2 CTAs/SM.
// EPI 0: QKV scatter (q/k/v single fp16). EPI 1: proj fp32 out + bias.
// ============================================================================
#define GST    144                // smem row stride bytes (64 fp16 + 16B pad)
#define GTILE  (128*GST)          // 18432
#define GSTG   (2*GTILE)          // 36864 (A,B)
#define SMEM_G (2*GSTG)           // 73728

__device__ __forceinline__ void g_cp(uint32_t sdst, const __half* __restrict__ g,
                                     int rb, int chunk, int tid)
{
    #pragma unroll
    for (int t = 0; t < 4; t++) {
        int idx = tid + (t << 8);            // 0..1023
        int row = idx >> 3, c8 = idx & 7;    // 8 x 16B per 128B row
        cp16(sdst + row * GST + c8 * 16,
             g + (size_t)(rb + row) * 1024 + chunk * 64 + c8 * 8);
    }
}

template<int EPI>
__global__ __launch_bounds__(256, 2)
void gemm_mma(const __half* __restrict__ A_g, const __half* __restrict__ B_g,
              const float* __restrict__ bias, float* __restrict__ out)
{
    extern __shared__ char smem[];
    const uint32_t sb = smem_u32(smem);
    const int tid = threadIdx.x, lane = tid & 31, wid = tid >> 5;
    const int bm = blockIdx.y * 128, bn = blockIdx.x * 128;
    const int wm = (wid >> 2) * 64, wn = (wid & 3) * 32;

    float acc[4][4][4];
    #pragma unroll
    for (int i = 0; i < 4; i++)
        #pragma unroll
        for (int j = 0; j < 4; j++)
            #pragma unroll
            for (int e = 0; e < 4; e++) acc[i][j][e] = 0.f;

    // prologue: stage 0 <- chunk 0
    g_cp(sb + 0*GTILE, A_g, bm, 0, tid);
    g_cp(sb + 1*GTILE, B_g, bn, 0, tid);
    CP_COMMIT();

    for (int c = 0; c < 16; c++) {
        CP_WAIT(0);          // chunk c resident
        __syncthreads();     // publish chunk c; retire reads of stage (c+1)&1
        if (c < 15) {        // copies for c+1 overlap compute of c
            uint32_t nb = sb + ((c + 1) & 1) * GSTG;
            g_cp(nb + 0*GTILE, A_g, bm, c + 1, tid);
            g_cp(nb + 1*GTILE, B_g, bn, c + 1, tid);
            CP_COMMIT();
        }

        const uint32_t base = sb + (c & 1) * GSTG;
        #pragma unroll
        for (int ks = 0; ks < 4; ks++) {
            const int k0 = ks * 16;
            uint32_t bf[8];
            #pragma unroll
            for (int np = 0; np < 2; np++) {
                int nrow = wn + np*16 + (lane & 7) + ((lane >> 4) & 1) * 8;
                int kcol = k0 + ((lane >> 3) & 1) * 8;
                ldsm4(&bf[np*4], base + GTILE + nrow * GST + kcol * 2);
            }
            #pragma unroll
            for (int mt = 0; mt < 4; mt++) {
                int arow = wm + mt*16 + (lane & 15);
                int acol = k0 + (lane >> 4) * 8;
                uint32_t af[4];
                ldsm4(af, base + arow * GST + acol * 2);
                #pragma unroll
                for (int nt = 0; nt < 4; nt++)
                    mma16816h(acc[mt][nt], af, &bf[nt*2]);
            }
        }
    }

    // epilogue
    #pragma unroll
    for (int mt = 0; mt < 4; mt++) {
        #pragma unroll
        for (int nt = 0; nt < 4; nt++) {
            float* cc = acc[mt][nt];
            int ng = bn + wn + nt*8 + (lane & 3) * 2;
            float2 bb = *(const float2*)(bias + ng);
            #pragma unroll
            for (int rh = 0; rh < 2; rh++) {
                int m = bm + wm + mt*16 + (lane >> 2) + rh * 8;
                float v0 = cc[rh*2] + bb.x, v1 = cc[rh*2+1] + bb.y;
                if (EPI == 0) {
                    int w = ng >> 10, hh = (ng >> 6) & 15, d = ng & 63;
                    int b_ = m >> 11, s = m & 2047;
                    size_t idx = ((size_t)((b_*NH + hh) * SEQ + s)) * HD + d;
                    if (w == 0) {
                        *(uint32_t*)(g_qh + idx) = hpair(v0 * SCALE, v1 * SCALE);
                    } else if (w == 1) {
                        *(uint32_t*)(g_kh + idx) = hpair(v0, v1);
                    } else {
                        *(uint32_t*)(g_vh + idx) = hpair(v0, v1);
                    }
                } else {
                    *(float2*)(out + (size_t)m * 1024 + ng) = make_float2(v0, v1);
                }
            }
        }
    }
}

// ============================================================================
// Flash attention (fp16, FROZEN shape): Q, K, V, P single fp16; fp32 accum.
// 3-stage KV ring, dual S accumulators. Grid (B*H=64, S/128=16), 8 warps.
// ============================================================================
#define AST   144                 // smem row stride bytes (64 fp16 + pad)
#define QTI   (128*AST)           // 18432
#define KTI   (64*AST)            // 9216
#define KVSTG (2*KTI)             // 18432 (Kh,Vh)
#define NKV   (SEQ/64)            // 32
#define SMEM_ATTN (QTI + 3*KVSTG) // 73728

__device__ __forceinline__ void kv_cp(uint32_t sbase, size_t gq, int t, int tid)
{
    #pragma unroll
    for (int it = 0; it < 2; it++) {
        int idx = tid + (it << 8);        // 0..511
        int row = idx >> 3, c8 = idx & 7; // 8 x 16B per 128B row
        size_t go = gq + (size_t)(t*64 + row) * HD + c8 * 8;
        uint32_t so = row * AST + c8 * 16;
        cp16(sbase + 0*KTI + so, g_kh + go);
        cp16(sbase + 1*KTI + so, g_vh + go);
    }
}

// S = Q K^T: batch all K frags per ks, single Q pass (8 indep accs)
#define ATTN_S(kvb, SAC) do {                                              \
    _Pragma("unroll")                                                      \
    for (int i = 0; i < 8; i++)                                            \
        _Pragma("unroll")                                                  \
        for (int e = 0; e < 4; e++) (SAC)[i][e] = 0.f;                     \
    _Pragma("unroll")                                                      \
    for (int ks = 0; ks < 4; ks++) {                                       \
        const int nr_ = (lane & 7) + ((lane >> 4) & 1) * 8;                \
        const int kc_ = ks*16 + ((lane >> 3) & 1) * 8;                     \
        uint32_t kb[4][4];                                                 \
        _Pragma("unroll")                                                  \
        for (int np = 0; np < 4; np++)                                     \
            ldsm4(kb[np], (kvb) + (np*16 + nr_)*AST + kc_*2);              \
        _Pragma("unroll")                                                  \
        for (int np = 0; np < 4; np++) {                                   \
            mma16816h((SAC)[2*np],   qfh[ks], kb[np]);                     \
            mma16816h((SAC)[2*np+1], qfh[ks], kb[np] + 2);                 \
        }                                                                  \
    }                                                                      \
} while (0)

// online softmax on SAC + rescale o
#define ATTN_SOFTMAX(SAC) do {                                             \
    float mx0 = (SAC)[0][0], mx1 = (SAC)[0][2];                            \
    _Pragma("unroll")                                                      \
    for (int nt = 0; nt < 8; nt++) {                                       \
        mx0 = fmaxf(mx0, fmaxf((SAC)[nt][0], (SAC)[nt][1]));               \
        mx1 = fmaxf(mx1, fmaxf((SAC)[nt][2], (SAC)[nt][3]));               \
    }                                                                      \
    mx0 = fmaxf(mx0, __shfl_xor_sync(0xffffffffu, mx0, 1));                \
    mx0 = fmaxf(mx0, __shfl_xor_sync(0xffffffffu, mx0, 2));                \
    mx1 = fmaxf(mx1, __shfl_xor_sync(0xffffffffu, mx1, 1));                \
    mx1 = fmaxf(mx1, __shfl_xor_sync(0xffffffffu, mx1, 2));                \
    float mn0 = fmaxf(m0, mx0), mn1 = fmaxf(m1, mx1);                      \
    float sc0 = __expf(m0 - mn0), sc1 = __expf(m1 - mn1);                  \
    m0 = mn0; m1 = mn1;                                                    \
    float s0 = 0.f, s1 = 0.f;                                              \
    _Pragma("unroll")                                                      \
    for (int nt = 0; nt < 8; nt++) {                                       \
        (SAC)[nt][0] = __expf((SAC)[nt][0] - mn0);                         \
        (SAC)[nt][1] = __expf((SAC)[nt][1] - mn0);                         \
        (SAC)[nt][2] = __expf((SAC)[nt][2] - mn1);                         \
        (SAC)[nt][3] = __expf((SAC)[nt][3] - mn1);                         \
        s0 += (SAC)[nt][0] + (SAC)[nt][1];                                 \
        s1 += (SAC)[nt][2] + (SAC)[nt][3];                                 \
    }                                                                      \
    s0 += __shfl_xor_sync(0xffffffffu, s0, 1);                             \
    s0 += __shfl_xor_sync(0xffffffffu, s0, 2);                             \
    s1 += __shfl_xor_sync(0xffffffffu, s1, 1);                             \
    s1 += __shfl_xor_sync(0xffffffffu, s1, 2);                             \
    l0 = l0 * sc0 + s0;                                                    \
    l1 = l1 * sc1 + s1;                                                    \
    _Pragma("unroll")                                                      \
    for (int nt = 0; nt < 8; nt++) {                                       \
        o[nt][0] *= sc0; o[nt][1] *= sc0;                                  \
        o[nt][2] *= sc1; o[nt][3] *= sc1;                                  \
    }                                                                      \
} while (0)

// O += P V: P single fp16, batch V frags per kp
#define ATTN_PV(kvb, SAC) do {                                             \
    _Pragma("unroll")                                                      \
    for (int kp = 0; kp < 4; kp++) {                                       \
        uint32_t pah[4];                                                   \
        {                                                                  \
            float* p0 = (SAC)[2*kp];                                       \
            float* p1 = (SAC)[2*kp + 1];                                   \
            pah[0] = hpair(p0[0], p0[1]);                                  \
            pah[1] = hpair(p0[2], p0[3]);                                  \
            pah[2] = hpair(p1[0], p1[1]);                                  \
            pah[3] = hpair(p1[2], p1[3]);                                  \
        }                                                                  \
        const int kr_ = kp*16 + (lane & 7) + ((lane >> 3) & 1) * 8;        \
        const int nc_ = ((lane >> 4) & 1) * 8;                             \
        uint32_t vb[4][4];                                                 \
        _Pragma("unroll")                                                  \
        for (int np = 0; np < 4; np++)                                     \
            ldsm4t(vb[np], (kvb) + KTI + kr_*AST + (np*16 + nc_)*2);       \
        _Pragma("unroll")                                                  \
        for (int np = 0; np < 4; np++) {                                   \
            mma16816h(o[2*np],   pah, vb[np]);                             \
            mma16816h(o[2*np+1], pah, vb[np] + 2);                         \
        }                                                                  \
    }                                                                      \
} while (0)

// one pipeline step: S(t+1) issue -> softmax(t) -> PV(t) -> ring rotate
#define ATTN_STEP(T, CUR, NXT) do {                                        \
    __syncthreads();          /* stage kv2 fully retired (PV(T-1) done) */ \
    if ((T) + 2 < NKV) {                                                   \
        kv_cp(kv2, gq, (T) + 2, tid); CP_COMMIT(); CP_WAIT(1);             \
    } else {                                                               \
        CP_WAIT(0);                                                        \
    }                                                                      \
    __syncthreads();          /* KV(T+1) visible to all */                 \
    if ((T) < NKV - 1) { ATTN_S(kv1, NXT); }                               \
    ATTN_SOFTMAX(CUR);                                                     \
    ATTN_PV(kv0, CUR);                                                     \
    { uint32_t r_ = kv0; kv0 = kv1; kv1 = kv2; kv2 = r_; }                 \
} while (0)

__global__ __launch_bounds__(256, 1)
void attn_mma()
{
    extern __shared__ char smem[];
    const uint32_t sb = smem_u32(smem);
    const int tid = threadIdx.x, lane = tid & 31, wid = tid >> 5;
    const int bh = blockIdx.x, q0 = blockIdx.y * 128;
    const int b = bh >> 4, h = bh & 15;
    const size_t gq = (size_t)bh * SEQ * HD;

    const uint32_t off_KV = QTI;
    uint32_t kv0 = sb + off_KV;            // holds KV(t)
    uint32_t kv1 = kv0 + KVSTG;            // holds KV(t+1)
    uint32_t kv2 = kv0 + 2*KVSTG;          // filling with KV(t+2)

    // prefetch KV(0), KV(1) first so Q's LDG latency overlaps
    kv_cp(kv0, gq, 0, tid); CP_COMMIT();
    kv_cp(kv1, gq, 1, tid); CP_COMMIT();

    // load Q tile (fp16), 128 rows x 64
    #pragma unroll
    for (int t = 0; t < 2; t++) {
        int idx = tid + (t << 8);          // 0..511
        int row = idx >> 2, c8 = (idx & 3) * 2;
        size_t go = gq + (size_t)(q0 + row) * HD + c8 * 8;
        *(uint4*)(smem + row*AST + c8*16)      = *(const uint4*)(g_qh + go);
        *(uint4*)(smem + row*AST + c8*16 + 16) = *(const uint4*)(g_qh + go + 8);
    }
    __syncthreads();

    // Q fragments to registers (persist whole kernel)
    uint32_t qfh[4][4];
    {
        int arow = wid*16 + (lane & 15);
        #pragma unroll
        for (int ks = 0; ks < 4; ks++)
            ldsm4(qfh[ks], sb + arow*AST + (ks*16 + (lane >> 4)*8) * 2);
    }

    float o[8][4];
    #pragma unroll
    for (int i = 0; i < 8; i++)
        #pragma unroll
        for (int e = 0; e < 4; e++) o[i][e] = 0.f;
    float m0 = -1e30f, m1 = -1e30f, l0 = 0.f, l1 = 0.f;

    float sA[8][4], sB[8][4];

    // KV(0) resident (KV(1) may still be in flight)
    CP_WAIT(1);
    __syncthreads();
    ATTN_S(kv0, sA);

    for (int t = 0; t < NKV; t += 2) {
        ATTN_STEP(t,     sA, sB);
        ATTN_STEP(t + 1, sB, sA);
    }

    // epilogue: O/l -> fp16 -> g_ah [B,S,D] (proj A is single fp16 now)
    float inv0 = 1.f / l0, inv1 = 1.f / l1;
    int r0 = q0 + wid*16 + (lane >> 2);
    int col0 = h * HD + (lane & 3) * 2;
    #pragma unroll
    for (int nt = 0; nt < 8; nt++) {
        int cg = col0 + nt * 8;
        #pragma unroll
        for (int rh = 0; rh < 2; rh++) {
            float inv = rh ? inv1 : inv0;
            float v0 = o[nt][rh*2] * inv, v1 = o[nt][rh*2+1] * inv;
            int s = r0 + rh * 8;
            size_t off = ((size_t)(b * SEQ + s)) * DMODEL + cg;
            *(uint32_t*)(g_ah + off) = hpair(v0, v1);
        }
    }
}

// ============================================================================
extern "C" void kernel_launch(void* const* d_in, const int* in_sizes, int n_in,
                              void* d_out, int out_size)
{
    const float* x      = (const float*)d_in[0];
    const float* W_qkv  = (const float*)d_in[1];
    const float* b_qkv  = (const float*)d_in[2];
    const float* W_proj = (const float*)d_in[3];
    const float* b_proj = (const float*)d_in[4];
    float* out = (float*)d_out;

    cudaFuncSetAttribute(gemm_mma<0>,
                         cudaFuncAttributeMaxDynamicSharedMemorySize, SMEM_G);
    cudaFuncSetAttribute(gemm_mma<1>,
                         cudaFuncAttributeMaxDynamicSharedMemorySize, SMEM_G);
    cudaFuncSetAttribute(attn_mma,
                         cudaFuncAttributeMaxDynamicSharedMemorySize, SMEM_ATTN);

    __half *xh, *wq, *wp, *ah;
    cudaGetSymbolAddress((void**)&xh, g_x);
    cudaGetSymbolAddress((void**)&wq, g_wq);
    cudaGetSymbolAddress((void**)&wp, g_wp);
    cudaGetSymbolAddress((void**)&ah, g_ah);

    conv_x  <<<8192, 256>>>(x, xh);
    split_tr<<<dim3(96, 32), 256>>>(W_qkv,  wq, 3072);
    split_tr<<<dim3(32, 32), 256>>>(W_proj, wp, 1024);

    gemm_mma<0><<<dim3(24, 64), 256, SMEM_G>>>(xh, wq, b_qkv, nullptr);
    attn_mma<<<dim3(64, 16), 256, SMEM_ATTN>>>();
    gemm_mma<1><<<dim3(8, 64), 256, SMEM_G>>>(ah, wp, b_proj, out);
}

// round 17
// speedup vs baseline: 1.4587x; 1.4587x over previous
#include <cuda_runtime.h>
#include <cuda_bf16.h>
#include <cuda_fp16.h>
#include <math.h>
#include <cstdint>

// Problem constants
#define BDIM   4
#define SEQ    2048
#define DMODEL 1024
#define NH     16
#define HD     64
#define SCALE  0.125f            // 1/sqrt(64)

// ============================================================================
// mma.sync / ldmatrix / cp.async helpers (base sm_80+ PTX, compute_103-safe)
// ============================================================================
__device__ __forceinline__ void mma16816h(float* c, const uint32_t* a, const uint32_t* b) {
    asm volatile("mma.sync.aligned.m16n8k16.row.col.f32.f16.f16.f32 "
        "{%0,%1,%2,%3}, {%4,%5,%6,%7}, {%8,%9}, {%0,%1,%2,%3};"
        : "+f"(c[0]), "+f"(c[1]), "+f"(c[2]), "+f"(c[3])
        : "r"(a[0]), "r"(a[1]), "r"(a[2]), "r"(a[3]), "r"(b[0]), "r"(b[1]));
}
__device__ __forceinline__ void ldsm4(uint32_t* r, uint32_t addr) {
    asm volatile("ldmatrix.sync.aligned.m8n8.x4.shared.b16 {%0,%1,%2,%3}, [%4];"
        : "=r"(r[0]), "=r"(r[1]), "=r"(r[2]), "=r"(r[3]) : "r"(addr));
}
__device__ __forceinline__ void ldsm4t(uint32_t* r, uint32_t addr) {
    asm volatile("ldmatrix.sync.aligned.m8n8.x4.trans.shared.b16 {%0,%1,%2,%3}, [%4];"
        : "=r"(r[0]), "=r"(r[1]), "=r"(r[2]), "=r"(r[3]) : "r"(addr));
}
__device__ __forceinline__ uint32_t smem_u32(const void* p) {
    uint32_t a;
    asm("{ .reg .u64 t; cvta.to.shared.u64 t, %1; cvt.u32.u64 %0, t; }"
        : "=r"(a) : "l"(p));
    return a;
}
__device__ __forceinline__ void cp16(uint32_t s, const void* g) {
    asm volatile("cp.async.cg.shared.global [%0], [%1], 16;" :: "r"(s), "l"(g));
}
#define CP_COMMIT() asm volatile("cp.async.commit_group;" ::: "memory")
#define CP_WAIT(n)  asm volatile("cp.async.wait_group %0;" :: "n"(n) : "memory")

__device__ __forceinline__ uint32_t hpair(float x, float y) {
    __half2 p;
    p.x = __float2half_rn(x); p.y = __float2half_rn(y);
    return *(uint32_t*)&p;
}

// ============================================================================
// scratch (device globals: no allocation allowed)
// ============================================================================
__device__ __half g_x  [8192*1024];          // X fp16 (single)
__device__ __half g_wq [3072*1024];          // W_qkv^T fp16 (single) [N,K]
__device__ __half g_wp [1024*1024];          // W_proj^T fp16 (single) [N,K]
__device__ __half g_qh[BDIM*NH*SEQ*HD];      // q fp16 (pre-scaled) [B,H,S,hd]
__device__ __half g_kh[BDIM*NH*SEQ*HD];      // k fp16
__device__ __half g_vh[BDIM*NH*SEQ*HD];      // v fp16
__device__ __half g_ah[8192*1024];           // attn out fp16 [B,S,D]

// ============================================================================
// Pre-pass: convert X to fp16
// ============================================================================
__global__ __launch_bounds__(256) void conv_x(const float* __restrict__ x,
                                              __half* __restrict__ dh)
{
    size_t i = ((size_t)blockIdx.x * 256 + threadIdx.x) * 4;
    float4 v = *(const float4*)(x + i);
    *(uint32_t*)(dh + i)     = hpair(v.x, v.y);
    *(uint32_t*)(dh + i + 2) = hpair(v.z, v.w);
}

// ============================================================================
// Pre-pass: transpose W [K=1024, N] -> W^T fp16 [N, 1024]
// ============================================================================
__global__ __launch_bounds__(256) void split_tr(const float* __restrict__ src,
                                                __half* __restrict__ dh,
                                                int N)
{
    __shared__ float t[32][33];
    const int n0 = blockIdx.x * 32, k0 = blockIdx.y * 32;
    const int tx = threadIdx.x & 31, ty = threadIdx.x >> 5;   // ty 0..7
    #pragma unroll
    for (int r = 0; r < 4; r++) {
        int k = k0 + ty + r * 8;
        t[ty + r * 8][tx] = src[(size_t)k * N + n0 + tx];
    }
    __syncthreads();
    #pragma unroll
    for (int r = 0; r < 4; r++) {
        int n = n0 + ty + r * 8;
        dh[(size_t)n * 1024 + k0 + tx] = __float2half_rn(t[tx][ty + r * 8]);
    }
}

// ============================================================================
// GEMM via mma.sync + cp.async (R14 PROVEN shape: BK=32, GST=80, 2-stage,
// one sync per chunk, 2 CTAs/SM). A,B single fp16.
// EPI 0: QKV scatter (q/k/v single fp16). EPI 1: proj fp32 out + bias.
// ============================================================================
#define GST    80                 // smem row stride bytes (32 fp16 + pad)
#define GTILE  (128*GST)          // 10240
#define GSTG   (2*GTILE)          // 20480 (A,B)
#define SMEM_G (2*GSTG)           // 40960

__device__ __forceinline__ void g_cp(uint32_t sdst, const __half* __restrict__ g,
                                     int rb, int chunk, int tid)
{
    #pragma unroll
    for (int t = 0; t < 2; t++) {
        int idx = tid + (t << 8);            // 0..511
        int row = idx >> 2, c4 = idx & 3;    // 4 x 16B per 64B row
        cp16(sdst + row * GST + c4 * 16,
             g + (size_t)(rb + row) * 1024 + chunk * 32 + c4 * 8);
    }
}

template<int EPI>
__global__ __launch_bounds__(256, 2)
void gemm_mma(const __half* __restrict__ A_g, const __half* __restrict__ B_g,
              const float* __restrict__ bias, float* __restrict__ out)
{
    extern __shared__ char smem[];
    const uint32_t sb = smem_u32(smem);
    const int tid = threadIdx.x, lane = tid & 31, wid = tid >> 5;
    const int bm = blockIdx.y * 128, bn = blockIdx.x * 128;
    const int wm = (wid >> 2) * 64, wn = (wid & 3) * 32;

    float acc[4][4][4];
    #pragma unroll
    for (int i = 0; i < 4; i++)
        #pragma unroll
        for (int j = 0; j < 4; j++)
            #pragma unroll
            for (int e = 0; e < 4; e++) acc[i][j][e] = 0.f;

    // prologue: stage 0 <- chunk 0
    g_cp(sb + 0*GTILE, A_g, bm, 0, tid);
    g_cp(sb + 1*GTILE, B_g, bn, 0, tid);
    CP_COMMIT();

    for (int c = 0; c < 32; c++) {
        CP_WAIT(0);          // chunk c resident
        __syncthreads();     // publish chunk c; retire reads of stage (c+1)&1
        if (c < 31) {        // copies for c+1 overlap compute of c
            uint32_t nb = sb + ((c + 1) & 1) * GSTG;
            g_cp(nb + 0*GTILE, A_g, bm, c + 1, tid);
            g_cp(nb + 1*GTILE, B_g, bn, c + 1, tid);
            CP_COMMIT();
        }

        const uint32_t base = sb + (c & 1) * GSTG;
        #pragma unroll
        for (int ks = 0; ks < 2; ks++) {
            const int k0 = ks * 16;
            uint32_t bf[8];
            #pragma unroll
            for (int np = 0; np < 2; np++) {
                int nrow = wn + np*16 + (lane & 7) + ((lane >> 4) & 1) * 8;
                int kcol = k0 + ((lane >> 3) & 1) * 8;
                ldsm4(&bf[np*4], base + GTILE + nrow * GST + kcol * 2);
            }
            #pragma unroll
            for (int mt = 0; mt < 4; mt++) {
                int arow = wm + mt*16 + (lane & 15);
                int acol = k0 + (lane >> 4) * 8;
                uint32_t af[4];
                ldsm4(af, base + arow * GST + acol * 2);
                #pragma unroll
                for (int nt = 0; nt < 4; nt++)
                    mma16816h(acc[mt][nt], af, &bf[nt*2]);
            }
        }
    }

    // epilogue
    #pragma unroll
    for (int mt = 0; mt < 4; mt++) {
        #pragma unroll
        for (int nt = 0; nt < 4; nt++) {
            float* cc = acc[mt][nt];
            int ng = bn + wn + nt*8 + (lane & 3) * 2;
            float2 bb = *(const float2*)(bias + ng);
            #pragma unroll
            for (int rh = 0; rh < 2; rh++) {
                int m = bm + wm + mt*16 + (lane >> 2) + rh * 8;
                float v0 = cc[rh*2] + bb.x, v1 = cc[rh*2+1] + bb.y;
                if (EPI == 0) {
                    int w = ng >> 10, hh = (ng >> 6) & 15, d = ng & 63;
                    int b_ = m >> 11, s = m & 2047;
                    size_t idx = ((size_t)((b_*NH + hh) * SEQ + s)) * HD + d;
                    if (w == 0) {
                        *(uint32_t*)(g_qh + idx) = hpair(v0 * SCALE, v1 * SCALE);
                    } else if (w == 1) {
                        *(uint32_t*)(g_kh + idx) = hpair(v0, v1);
                    } else {
                        *(uint32_t*)(g_vh + idx) = hpair(v0, v1);
                    }
                } else {
                    *(float2*)(out + (size_t)m * 1024 + ng) = make_float2(v0, v1);
                }
            }
        }
    }
}

// ============================================================================
// Flash attention (fp16, FROZEN shape): Q, K, V, P single fp16; fp32 accum.
// 3-stage KV ring, dual S accumulators. Grid (B*H=64, S/128=16), 8 warps.
// ============================================================================
#define AST   144                 // smem row stride bytes (64 fp16 + pad)
#define QTI   (128*AST)           // 18432
#define KTI   (64*AST)            // 9216
#define KVSTG (2*KTI)             // 18432 (Kh,Vh)
#define NKV   (SEQ/64)            // 32
#define SMEM_ATTN (QTI + 3*KVSTG) // 73728

__device__ __forceinline__ void kv_cp(uint32_t sbase, size_t gq, int t, int tid)
{
    #pragma unroll
    for (int it = 0; it < 2; it++) {
        int idx = tid + (it << 8);        // 0..511
        int row = idx >> 3, c8 = idx & 7; // 8 x 16B per 128B row
        size_t go = gq + (size_t)(t*64 + row) * HD + c8 * 8;
        uint32_t so = row * AST + c8 * 16;
        cp16(sbase + 0*KTI + so, g_kh + go);
        cp16(sbase + 1*KTI + so, g_vh + go);
    }
}

// S = Q K^T: batch all K frags per ks, single Q pass (8 indep accs)
#define ATTN_S(kvb, SAC) do {                                              \
    _Pragma("unroll")                                                      \
    for (int i = 0; i < 8; i++)                                            \
        _Pragma("unroll")                                                  \
        for (int e = 0; e < 4; e++) (SAC)[i][e] = 0.f;                     \
    _Pragma("unroll")                                                      \
    for (int ks = 0; ks < 4; ks++) {                                       \
        const int nr_ = (lane & 7) + ((lane >> 4) & 1) * 8;                \
        const int kc_ = ks*16 + ((lane >> 3) & 1) * 8;                     \
        uint32_t kb[4][4];                                                 \
        _Pragma("unroll")                                                  \
        for (int np = 0; np < 4; np++)                                     \
            ldsm4(kb[np], (kvb) + (np*16 + nr_)*AST + kc_*2);              \
        _Pragma("unroll")                                                  \
        for (int np = 0; np < 4; np++) {                                   \
            mma16816h((SAC)[2*np],   qfh[ks], kb[np]);                     \
            mma16816h((SAC)[2*np+1], qfh[ks], kb[np] + 2);                 \
        }                                                                  \
    }                                                                      \
} while (0)

// online softmax on SAC + rescale o
#define ATTN_SOFTMAX(SAC) do {                                             \
    float mx0 = (SAC)[0][0], mx1 = (SAC)[0][2];                            \
    _Pragma("unroll")                                                      \
    for (int nt = 0; nt < 8; nt++) {                                       \
        mx0 = fmaxf(mx0, fmaxf((SAC)[nt][0], (SAC)[nt][1]));               \
        mx1 = fmaxf(mx1, fmaxf((SAC)[nt][2], (SAC)[nt][3]));               \
    }                                                                      \
    mx0 = fmaxf(mx0, __shfl_xor_sync(0xffffffffu, mx0, 1));                \
    mx0 = fmaxf(mx0, __shfl_xor_sync(0xffffffffu, mx0, 2));                \
    mx1 = fmaxf(mx1, __shfl_xor_sync(0xffffffffu, mx1, 1));                \
    mx1 = fmaxf(mx1, __shfl_xor_sync(0xffffffffu, mx1, 2));                \
    float mn0 = fmaxf(m0, mx0), mn1 = fmaxf(m1, mx1);                      \
    float sc0 = __expf(m0 - mn0), sc1 = __expf(m1 - mn1);                  \
    m0 = mn0; m1 = mn1;                                                    \
    float s0 = 0.f, s1 = 0.f;                                              \
    _Pragma("unroll")                                                      \
    for (int nt = 0; nt < 8; nt++) {                                       \
        (SAC)[nt][0] = __expf((SAC)[nt][0] - mn0);                         \
        (SAC)[nt][1] = __expf((SAC)[nt][1] - mn0);                         \
        (SAC)[nt][2] = __expf((SAC)[nt][2] - mn1);                         \
        (SAC)[nt][3] = __expf((SAC)[nt][3] - mn1);                         \
        s0 += (SAC)[nt][0] + (SAC)[nt][1];                                 \
        s1 += (SAC)[nt][2] + (SAC)[nt][3];                                 \
    }                                                                      \
    s0 += __shfl_xor_sync(0xffffffffu, s0, 1);                             \
    s0 += __shfl_xor_sync(0xffffffffu, s0, 2);                             \
    s1 += __shfl_xor_sync(0xffffffffu, s1, 1);                             \
    s1 += __shfl_xor_sync(0xffffffffu, s1, 2);                             \
    l0 = l0 * sc0 + s0;                                                    \
    l1 = l1 * sc1 + s1;                                                    \
    _Pragma("unroll")                                                      \
    for (int nt = 0; nt < 8; nt++) {                                       \
        o[nt][0] *= sc0; o[nt][1] *= sc0;                                  \
        o[nt][2] *= sc1; o[nt][3] *= sc1;                                  \
    }                                                                      \
} while (0)

// O += P V: P single fp16, batch V frags per kp
#define ATTN_PV(kvb, SAC) do {                                             \
    _Pragma("unroll")                                                      \
    for (int kp = 0; kp < 4; kp++) {                                       \
        uint32_t pah[4];                                                   \
        {                                                                  \
            float* p0 = (SAC)[2*kp];                                       \
            float* p1 = (SAC)[2*kp + 1];                                   \
            pah[0] = hpair(p0[0], p0[1]);                                  \
            pah[1] = hpair(p0[2], p0[3]);                                  \
            pah[2] = hpair(p1[0], p1[1]);                                  \
            pah[3] = hpair(p1[2], p1[3]);                                  \
        }                                                                  \
        const int kr_ = kp*16 + (lane & 7) + ((lane >> 3) & 1) * 8;        \
        const int nc_ = ((lane >> 4) & 1) * 8;                             \
        uint32_t vb[4][4];                                                 \
        _Pragma("unroll")                                                  \
        for (int np = 0; np < 4; np++)                                     \
            ldsm4t(vb[np], (kvb) + KTI + kr_*AST + (np*16 + nc_)*2);       \
        _Pragma("unroll")                                                  \
        for (int np = 0; np < 4; np++) {                                   \
            mma16816h(o[2*np],   pah, vb[np]);                             \
            mma16816h(o[2*np+1], pah, vb[np] + 2);                         \
        }                                                                  \
    }                                                                      \
} while (0)

// one pipeline step: S(t+1) issue -> softmax(t) -> PV(t) -> ring rotate
#define ATTN_STEP(T, CUR, NXT) do {                                        \
    __syncthreads();          /* stage kv2 fully retired (PV(T-1) done) */ \
    if ((T) + 2 < NKV) {                                                   \
        kv_cp(kv2, gq, (T) + 2, tid); CP_COMMIT(); CP_WAIT(1);             \
    } else {                                                               \
        CP_WAIT(0);                                                        \
    }                                                                      \
    __syncthreads();          /* KV(T+1) visible to all */                 \
    if ((T) < NKV - 1) { ATTN_S(kv1, NXT); }                               \
    ATTN_SOFTMAX(CUR);                                                     \
    ATTN_PV(kv0, CUR);                                                     \
    { uint32_t r_ = kv0; kv0 = kv1; kv1 = kv2; kv2 = r_; }                 \
} while (0)

__global__ __launch_bounds__(256, 1)
void attn_mma()
{
    extern __shared__ char smem[];
    const uint32_t sb = smem_u32(smem);
    const int tid = threadIdx.x, lane = tid & 31, wid = tid >> 5;
    const int bh = blockIdx.x, q0 = blockIdx.y * 128;
    const int b = bh >> 4, h = bh & 15;
    const size_t gq = (size_t)bh * SEQ * HD;

    const uint32_t off_KV = QTI;
    uint32_t kv0 = sb + off_KV;            // holds KV(t)
    uint32_t kv1 = kv0 + KVSTG;            // holds KV(t+1)
    uint32_t kv2 = kv0 + 2*KVSTG;          // filling with KV(t+2)

    // prefetch KV(0), KV(1) first so Q's LDG latency overlaps
    kv_cp(kv0, gq, 0, tid); CP_COMMIT();
    kv_cp(kv1, gq, 1, tid); CP_COMMIT();

    // load Q tile (fp16), 128 rows x 64
    #pragma unroll
    for (int t = 0; t < 2; t++) {
        int idx = tid + (t << 8);          // 0..511
        int row = idx >> 2, c8 = (idx & 3) * 2;
        size_t go = gq + (size_t)(q0 + row) * HD + c8 * 8;
        *(uint4*)(smem + row*AST + c8*16)      = *(const uint4*)(g_qh + go);
        *(uint4*)(smem + row*AST + c8*16 + 16) = *(const uint4*)(g_qh + go + 8);
    }
    __syncthreads();

    // Q fragments to registers (persist whole kernel)
    uint32_t qfh[4][4];
    {
        int arow = wid*16 + (lane & 15);
        #pragma unroll
        for (int ks = 0; ks < 4; ks++)
            ldsm4(qfh[ks], sb + arow*AST + (ks*16 + (lane >> 4)*8) * 2);
    }

    float o[8][4];
    #pragma unroll
    for (int i = 0; i < 8; i++)
        #pragma unroll
        for (int e = 0; e < 4; e++) o[i][e] = 0.f;
    float m0 = -1e30f, m1 = -1e30f, l0 = 0.f, l1 = 0.f;

    float sA[8][4], sB[8][4];

    // KV(0) resident (KV(1) may still be in flight)
    CP_WAIT(1);
    __syncthreads();
    ATTN_S(kv0, sA);

    for (int t = 0; t < NKV; t += 2) {
        ATTN_STEP(t,     sA, sB);
        ATTN_STEP(t + 1, sB, sA);
    }

    // epilogue: O/l -> fp16 -> g_ah [B,S,D] (proj A single fp16)
    float inv0 = 1.f / l0, inv1 = 1.f / l1;
    int r0 = q0 + wid*16 + (lane >> 2);
    int col0 = h * HD + (lane & 3) * 2;
    #pragma unroll
    for (int nt = 0; nt < 8; nt++) {
        int cg = col0 + nt * 8;
        #pragma unroll
        for (int rh = 0; rh < 2; rh++) {
            float inv = rh ? inv1 : inv0;
            float v0 = o[nt][rh*2] * inv, v1 = o[nt][rh*2+1] * inv;
            int s = r0 + rh * 8;
            size_t off = ((size_t)(b * SEQ + s)) * DMODEL + cg;
            *(uint32_t*)(g_ah + off) = hpair(v0, v1);
        }
    }
}

// ============================================================================
extern "C" void kernel_launch(void* const* d_in, const int* in_sizes, int n_in,
                              void* d_out, int out_size)
{
    const float* x      = (const float*)d_in[0];
    const float* W_qkv  = (const float*)d_in[1];
    const float* b_qkv  = (const float*)d_in[2];
    const float* W_proj = (const float*)d_in[3];
    const float* b_proj = (const float*)d_in[4];
    float* out = (float*)d_out;

    cudaFuncSetAttribute(gemm_mma<0>,
                         cudaFuncAttributeMaxDynamicSharedMemorySize, SMEM_G);
    cudaFuncSetAttribute(gemm_mma<1>,
                         cudaFuncAttributeMaxDynamicSharedMemorySize, SMEM_G);
    cudaFuncSetAttribute(attn_mma,
                         cudaFuncAttributeMaxDynamicSharedMemorySize, SMEM_ATTN);

    __half *xh, *wq, *wp, *ah;
    cudaGetSymbolAddress((void**)&xh, g_x);
    cudaGetSymbolAddress((void**)&wq, g_wq);
    cudaGetSymbolAddress((void**)&wp, g_wp);
    cudaGetSymbolAddress((void**)&ah, g_ah);

    conv_x  <<<8192, 256>>>(x, xh);
    split_tr<<<dim3(96, 32), 256>>>(W_qkv,  wq, 3072);
    split_tr<<<dim3(32, 32), 256>>>(W_proj, wp, 1024);

    gemm_mma<0><<<dim3(24, 64), 256, SMEM_G>>>(xh, wq, b_qkv, nullptr);
    attn_mma<<<dim3(64, 16), 256, SMEM_ATTN>>>();
    gemm_mma<1><<<dim3(8, 64), 256, SMEM_G>>>(ah, wp, b_proj, out);
}